// round 15
// baseline (speedup 1.0000x reference)
#include <cuda_runtime.h>
#include <cuda_fp16.h>
#include <cstdint>

#define BATCH   8
#define CCH     320
#define HWD     160
#define DD      160
#define NHEADS  5
#define HDIM    32
#define PIX     (HWD*HWD)
#define MTOK    (BATCH*PIX)
#define OUTB    (HWD*HWD*HWD)
#define QK_SCALE 0.17677669529663687f

// ---------------- scratch ----------------------------------------------------
__device__ __half g_xn[(size_t)MTOK * CCH];      // LN output, fp16
__device__ __half g_y[2][(size_t)MTOK * DD];     // [0]=yh, [1]=yv permuted (fp16)
__device__ __half g_wc_f[(size_t)CCH * CCH];
__device__ __half g_wq_f[6][(size_t)DD * DD];

// ---------------- PTX helpers --------------------------------------------------
__device__ __forceinline__ uint32_t smem_u32(const void* p) {
    uint32_t a;
    asm("{ .reg .u64 t; cvta.to.shared.u64 t, %1; cvt.u32.u64 %0, t; }"
        : "=r"(a) : "l"(p));
    return a;
}
__device__ __forceinline__ void cp16(uint32_t dst, const void* src) {
    asm volatile("cp.async.cg.shared.global [%0], [%1], 16;"
                 :: "r"(dst), "l"(src) : "memory");
}
#define CP_COMMIT() asm volatile("cp.async.commit_group;" ::: "memory")
#define CP_WAIT(n)  asm volatile("cp.async.wait_group %0;" :: "n"(n) : "memory")

__device__ __forceinline__ void ldm_x4(uint32_t* r, uint32_t addr) {
    asm volatile("ldmatrix.sync.aligned.m8n8.x4.shared.b16 {%0,%1,%2,%3}, [%4];"
        : "=r"(r[0]), "=r"(r[1]), "=r"(r[2]), "=r"(r[3]) : "r"(addr));
}
__device__ __forceinline__ void ldm_x4_t(uint32_t* r, uint32_t addr) {
    asm volatile("ldmatrix.sync.aligned.m8n8.x4.trans.shared.b16 {%0,%1,%2,%3}, [%4];"
        : "=r"(r[0]), "=r"(r[1]), "=r"(r[2]), "=r"(r[3]) : "r"(addr));
}
__device__ __forceinline__ void mma_f16(float* d, const uint32_t* a, const uint32_t* b) {
    asm volatile(
        "mma.sync.aligned.m16n8k16.row.col.f32.f16.f16.f32 "
        "{%0,%1,%2,%3}, {%4,%5,%6,%7}, {%8,%9}, {%0,%1,%2,%3};"
        : "+f"(d[0]), "+f"(d[1]), "+f"(d[2]), "+f"(d[3])
        : "r"(a[0]), "r"(a[1]), "r"(a[2]), "r"(a[3]), "r"(b[0]), "r"(b[1]));
}

// 64B-row XOR swizzle (fp16 tiles)
__device__ __forceinline__ uint32_t swz(uint32_t row, uint32_t unit) {
    return row * 64u + ((unit ^ ((row >> 1) & 3u)) << 4);
}
__device__ __forceinline__ uint32_t hf2u(float a, float b) {
    __half2 t = __floats2half2_rn(a, b);
    return *reinterpret_cast<uint32_t*>(&t);
}
// fp32 O-plane swizzle: 128B rows (32 e-floats), 16B units rotated by s
__device__ __forceinline__ uint32_t oswz(uint32_t s, uint32_t e) {
    return s * 128u + ((((e >> 2) ^ (s & 7u)) & 7u) << 4) + (e & 3u) * 4u;
}

// ---------------- kernel 1: fused LN (stats + normalize + fp16) -----------------
__global__ __launch_bounds__(256) void ln_fused_kernel(
    const float* __restrict__ x, const float* __restrict__ lng,
    const float* __restrict__ lnb)
{
    __shared__ float s[CCH][33];
    __shared__ float ps1[8][32], ps2[8][32];
    __shared__ float mu_s[32], rs_s[32];
    int tok0 = blockIdx.x * 32;
    int b = tok0 / PIX;
    int pix0 = tok0 - b * PIX;
    int tid = threadIdx.x;
    const float* xb = x + (size_t)b * CCH * PIX + pix0;

#pragma unroll
    for (int i = 0; i < 40; i++) {
        int idx = tid + i * 256;
        int c = idx >> 5, t = idx & 31;
        s[c][t] = xb[(size_t)c * PIX + t];
    }
    __syncthreads();

    {
        int t = tid & 31, part = tid >> 5;
        float s1 = 0.f, s2 = 0.f;
#pragma unroll
        for (int i = 0; i < 40; i++) {
            float v = s[part * 40 + i][t];
            s1 += v; s2 += v * v;
        }
        ps1[part][t] = s1; ps2[part][t] = s2;
    }
    __syncthreads();
    if (tid < 32) {
        float a1 = 0.f, a2 = 0.f;
#pragma unroll
        for (int p = 0; p < 8; p++) { a1 += ps1[p][tid]; a2 += ps2[p][tid]; }
        float mu = a1 * (1.0f / CCH);
        mu_s[tid] = mu;
        rs_s[tid] = rsqrtf(a2 * (1.0f / CCH) - mu * mu + 1e-5f);
    }
    __syncthreads();

    int w = tid >> 5, lane = tid & 31;
#pragma unroll
    for (int i = 0; i < 4; i++) {
        int tt = w + 8 * i;
        int m = tok0 + tt;
        float mu = mu_s[tt], rs = rs_s[tt];
#pragma unroll
        for (int j = 0; j < 5; j++) {
            int c = lane * 2 + 64 * j;
            float v0 = (s[c][tt]     - mu) * rs * lng[c]     + lnb[c];
            float v1 = (s[c + 1][tt] - mu) * rs * lng[c + 1] + lnb[c + 1];
            *reinterpret_cast<uint32_t*>(&g_xn[(size_t)m * CCH + c]) = hf2u(v0, v1);
        }
    }
}

// ---------------- kernel 2: weights to fp16 -------------------------------------
__global__ __launch_bounds__(256) void wconv_kernel(
    const float* __restrict__ cw,
    const float* __restrict__ w0, const float* __restrict__ w1,
    const float* __restrict__ w2, const float* __restrict__ w3,
    const float* __restrict__ w4, const float* __restrict__ w5)
{
    int i = blockIdx.x * 256 + threadIdx.x;
    if (i < CCH * CCH) {
        g_wc_f[i] = __float2half_rn(cw[i]);
    } else {
        int j = i - CCH * CCH;
        if (j < 6 * DD * DD) {
            int z = j / (DD * DD);
            int rem = j - z * (DD * DD);
            const float* ws = (z == 0) ? w0 : (z == 1) ? w1 : (z == 2) ? w2
                             : (z == 3) ? w3 : (z == 4) ? w4 : w5;
            g_wq_f[z][rem] = __float2half_rn(ws[rem]);
        }
    }
}

// ---------------- conv GEMM (pipelined, unchanged) --------------------------------
#define STG_B  4096
#define STG_SZ 14336
#define GEMM_SMEM (4 * STG_SZ)

__device__ __forceinline__ void stage_load(uint32_t st,
    const __half* A, int astride, const __half* B, int bstride, int k0)
{
    int tid = threadIdx.x;
#pragma unroll
    for (int i = 0; i < 4; i++) {
        int idx = tid + i * 256;
        if (idx < 256) {
            int r = idx >> 2;
            int u = idx & 3;
            cp16(st + swz(r, u), A + (size_t)r * astride + k0 + u * 8);
        } else if (idx < 896) {
            int j = idx - 256;
            int r = j >> 2;
            int u = j & 3;
            cp16(st + STG_B + swz(r, u), B + (size_t)r * bstride + k0 + u * 8);
        }
    }
}

__device__ __forceinline__ void stage_compute(uint32_t st, int lane, int wm, int wn,
                                              float acc[10][4])
{
    uint32_t af[2][4];
    int arow = wm * 16 + (lane & 15);
#pragma unroll
    for (int ks = 0; ks < 2; ks++)
        ldm_x4(af[ks], st + swz(arow, (lane >> 4) + 2 * ks));
#pragma unroll
    for (int g = 0; g < 5; g++) {
        int brow = wn * 80 + g * 16 + (lane & 7) + ((lane >> 4) << 3);
        int bu = (lane >> 3) & 1;
#pragma unroll
        for (int ks = 0; ks < 2; ks++) {
            uint32_t bf[4];
            ldm_x4(bf, st + STG_B + swz(brow, bu + 2 * ks));
#pragma unroll
            for (int h2 = 0; h2 < 2; h2++)
                mma_f16(acc[g * 2 + h2], af[ks], bf + 2 * h2);
        }
    }
}

__global__ void __launch_bounds__(256, 2) conv_gemm_mma(const float* __restrict__ bias)
{
    extern __shared__ __align__(128) char smem[];
    uint32_t sb = smem_u32(smem);
    int ntile = blockIdx.x;
    int m0 = blockIdx.y * 64;
    int lane = threadIdx.x & 31;
    int wm = (threadIdx.x >> 5) & 3;
    int wn = threadIdx.x >> 7;
    const __half* A = g_xn + (size_t)m0 * CCH;
    const __half* B = g_wc_f + (size_t)(ntile * 160) * CCH;

    float acc[10][4];
#pragma unroll
    for (int a = 0; a < 10; a++)
#pragma unroll
        for (int c = 0; c < 4; c++) acc[a][c] = 0.f;

#pragma unroll
    for (int p = 0; p < 3; p++) {
        stage_load(sb + p * STG_SZ, A, CCH, B, CCH, p * 32);
        CP_COMMIT();
    }
    for (int c = 0; c < 10; c++) {
        if (c + 3 < 10) { CP_WAIT(2); } else { CP_WAIT(0); }
        __syncthreads();
        if (c + 3 < 10) {
            stage_load(sb + ((c + 3) & 3) * STG_SZ, A, CCH, B, CCH, (c + 3) * 32);
            CP_COMMIT();
        }
        stage_compute(sb + (c & 3) * STG_SZ, lane, wm, wn, acc);
    }

#pragma unroll
    for (int hf = 0; hf < 2; hf++) {
        int m = m0 + wm * 16 + (lane >> 2) + 8 * hf;
        size_t drow;
        if (ntile == 0) drow = (size_t)m;
        else {
            int b = m / PIX; int rem = m - b * PIX;
            int hh = rem / HWD; int ww = rem - hh * HWD;
            drow = ((size_t)b * HWD + ww) * HWD + hh;
        }
        __half* dh = g_y[ntile] + drow * DD;
#pragma unroll
        for (int j = 0; j < 10; j++) {
            int col = wn * 80 + j * 8 + (lane & 3) * 2;
            float v0 = acc[j][hf * 2 + 0] + bias[ntile * 160 + col];
            float v1 = acc[j][hf * 2 + 1] + bias[ntile * 160 + col + 1];
            *reinterpret_cast<uint32_t*>(dh + col) = hf2u(v0, v1);
        }
    }
}

// ---------------- kernel 3: FUSED qkv + attention ---------------------------------
// CTA = (head, sequence, branch). 320 threads = 10 warps, each owns 16 query rows.
// smem (100KB): Y 5 planes 50K | Wq,Wk,Wv 3x10K | k 10K | v 10K.
// All 3 projection GEMMs merged (shared A frags, 3 accumulators). q/P in regs.
// Branch-0 output staged through smem for coalesced float4 stores.
#define FY   0
#define FW   51200
#define FK   81920
#define FV   92160
#define FUSED_SMEM 102400

__global__ void __launch_bounds__(320, 2) fused_qkv_attn(
    float* __restrict__ out,
    const float* __restrict__ bq_h, const float* __restrict__ bk_h,
    const float* __restrict__ bv_h, const float* __restrict__ bq_v,
    const float* __restrict__ bk_v, const float* __restrict__ bv_v)
{
    extern __shared__ __align__(128) char smem[];
    uint32_t sb = smem_u32(smem);
    int h      = blockIdx.x;          // head (fastest -> L2 reuse of Y)
    int bi     = blockIdx.y;          // sequence
    int branch = blockIdx.z;
    int tid = threadIdx.x, lane = tid & 31, w = tid >> 5;   // w: 0..9
    size_t seqBase = (size_t)bi * HWD;
    int z0 = branch * 3;

    const __half* ybase = &g_y[branch][seqBase * DD];
    const __half* wsrc[3] = {
        &g_wq_f[z0 + 0][(size_t)h * HDIM * DD],
        &g_wq_f[z0 + 1][(size_t)h * HDIM * DD],
        &g_wq_f[z0 + 2][(size_t)h * HDIM * DD]};
    const float* bq = (branch ? bq_v : bq_h) + h * HDIM;
    const float* bk = (branch ? bk_v : bk_h) + h * HDIM;
    const float* bv = (branch ? bv_v : bv_h) + h * HDIM;

    // ---- prologue: Y (3200 cp16, 5 planes) + all W (1920 cp16), one group ----
#pragma unroll
    for (int i = 0; i < 10; i++) {
        int idx = tid + i * 320;
        int plane = idx / 640;
        int rem = idx - plane * 640;
        int r = rem >> 2, u = rem & 3;
        cp16(sb + FY + plane * 10240 + swz(r, u),
             ybase + (size_t)r * DD + plane * 32 + u * 8);
    }
#pragma unroll
    for (int i = 0; i < 6; i++) {
        int idx = tid + i * 320;
        int g = idx / 640;
        int rem = idx - g * 640;
        int plane = rem >> 7;
        int rr = rem & 127;
        int r = rr >> 2, u = rr & 3;
        cp16(sb + FW + g * 10240 + plane * 2048 + swz(r, u),
             wsrc[g] + (size_t)r * DD + plane * 32 + u * 8);
    }
    CP_COMMIT();
    CP_WAIT(0);
    __syncthreads();                 // barrier #1

    int arow = w * 16 + (lane & 15);
    int au   = (lane >> 4);
    int prow = w * 16 + (lane >> 2);
    uint32_t brow_b = (lane & 7) + ((lane >> 4) << 3);
    uint32_t bu = (lane >> 3) & 1;

    // ---- merged q+k+v GEMMs (shared A frags, 3 accumulators) ----
    uint32_t qf[2][4];
    {
        float accq[4][4], acck[4][4], accv[4][4];
#pragma unroll
        for (int a = 0; a < 4; a++)
#pragma unroll
            for (int e = 0; e < 4; e++) {
                accq[a][e] = 0.f; acck[a][e] = 0.f; accv[a][e] = 0.f;
            }

#pragma unroll
        for (int c = 0; c < 5; c++) {
            uint32_t af[2][4];
#pragma unroll
            for (int ke = 0; ke < 2; ke++)
                ldm_x4(af[ke], sb + FY + c * 10240 + swz(arow, au + 2 * ke));
#pragma unroll
            for (int g2 = 0; g2 < 2; g2++) {
                uint32_t brow = g2 * 16 + brow_b;
#pragma unroll
                for (int ke = 0; ke < 2; ke++) {
                    uint32_t bfq[4], bfk[4], bfv[4];
                    ldm_x4(bfq, sb + FW + 0 * 10240 + c * 2048 + swz(brow, bu + 2 * ke));
                    ldm_x4(bfk, sb + FW + 1 * 10240 + c * 2048 + swz(brow, bu + 2 * ke));
                    ldm_x4(bfv, sb + FW + 2 * 10240 + c * 2048 + swz(brow, bu + 2 * ke));
#pragma unroll
                    for (int h2 = 0; h2 < 2; h2++) {
                        mma_f16(accq[g2 * 2 + h2], af[ke], bfq + 2 * h2);
                        mma_f16(acck[g2 * 2 + h2], af[ke], bfk + 2 * h2);
                        mma_f16(accv[g2 * 2 + h2], af[ke], bfv + 2 * h2);
                    }
                }
            }
        }

        // k, v -> smem planes (warp-private rows)
#pragma unroll
        for (int j = 0; j < 4; j++) {
            int n0 = j * 8 + (lane & 3) * 2;
            float bk0 = bk[n0], bk1 = bk[n0 + 1];
            float bv0 = bv[n0], bv1 = bv[n0 + 1];
#pragma unroll
            for (int hf = 0; hf < 2; hf++) {
                uint32_t off = swz(prow + 8 * hf, j) + (lane & 3) * 4;
                *reinterpret_cast<uint32_t*>(smem + FK + off) =
                    hf2u(acck[j][hf * 2 + 0] + bk0, acck[j][hf * 2 + 1] + bk1);
                *reinterpret_cast<uint32_t*>(smem + FV + off) =
                    hf2u(accv[j][hf * 2 + 0] + bv0, accv[j][hf * 2 + 1] + bv1);
            }
        }

        // q -> register A-fragments (bias + QK_SCALE folded)
        int c2 = (lane & 3) * 2;
#pragma unroll
        for (int ke = 0; ke < 2; ke++) {
            float blo0 = bq[16 * ke + c2],     blo1 = bq[16 * ke + c2 + 1];
            float bhi0 = bq[16 * ke + 8 + c2], bhi1 = bq[16 * ke + 8 + c2 + 1];
            qf[ke][0] = hf2u((accq[2 * ke][0] + blo0) * QK_SCALE,
                             (accq[2 * ke][1] + blo1) * QK_SCALE);
            qf[ke][1] = hf2u((accq[2 * ke][2] + blo0) * QK_SCALE,
                             (accq[2 * ke][3] + blo1) * QK_SCALE);
            qf[ke][2] = hf2u((accq[2 * ke + 1][0] + bhi0) * QK_SCALE,
                             (accq[2 * ke + 1][1] + bhi1) * QK_SCALE);
            qf[ke][3] = hf2u((accq[2 * ke + 1][2] + bhi0) * QK_SCALE,
                             (accq[2 * ke + 1][3] + bhi1) * QK_SCALE);
        }
    }
    __syncthreads();                 // barrier #2: k,v planes visible

    // ---- attention: register q/P, smem K/V, V prefetched ahead of exp ----
    float O[4][4];
#pragma unroll
    for (int a = 0; a < 4; a++)
#pragma unroll
        for (int e = 0; e < 4; e++) O[a][e] = 0.f;
    float lsum[2] = {0.f, 0.f};

#pragma unroll
    for (int tb = 0; tb < 5; tb++) {
        int t0 = tb * 32;
        float S[4][4];
#pragma unroll
        for (int a = 0; a < 4; a++)
#pragma unroll
            for (int e = 0; e < 4; e++) S[a][e] = 0.f;

#pragma unroll
        for (int g = 0; g < 2; g++) {
            int brow = t0 + g * 16 + brow_b;
#pragma unroll
            for (int ke = 0; ke < 2; ke++) {
                uint32_t kf[4];
                ldm_x4(kf, sb + FK + swz(brow, bu + 2 * ke));
#pragma unroll
                for (int h2 = 0; h2 < 2; h2++)
                    mma_f16(S[g * 2 + h2], qf[ke], kf + 2 * h2);
            }
        }

        uint32_t vf[2][2][4];
#pragma unroll
        for (int kt = 0; kt < 2; kt++)
#pragma unroll
            for (int ge = 0; ge < 2; ge++) {
                int vrow = t0 + kt * 16 + (lane & 15);
                int vu = ge * 2 + (lane >> 4);
                ldm_x4_t(vf[kt][ge], sb + FV + swz(vrow, vu));
            }

        float P[4][4];
#pragma unroll
        for (int j = 0; j < 4; j++) {
            P[j][0] = __expf(S[j][0]);
            P[j][1] = __expf(S[j][1]);
            P[j][2] = __expf(S[j][2]);
            P[j][3] = __expf(S[j][3]);
            lsum[0] += P[j][0] + P[j][1];
            lsum[1] += P[j][2] + P[j][3];
        }
        uint32_t pf[2][4];
#pragma unroll
        for (int kt = 0; kt < 2; kt++) {
            pf[kt][0] = hf2u(P[2 * kt][0],     P[2 * kt][1]);
            pf[kt][1] = hf2u(P[2 * kt][2],     P[2 * kt][3]);
            pf[kt][2] = hf2u(P[2 * kt + 1][0], P[2 * kt + 1][1]);
            pf[kt][3] = hf2u(P[2 * kt + 1][2], P[2 * kt + 1][3]);
        }

#pragma unroll
        for (int kt = 0; kt < 2; kt++)
#pragma unroll
            for (int ge = 0; ge < 2; ge++)
#pragma unroll
                for (int h2 = 0; h2 < 2; h2++)
                    mma_f16(O[ge * 2 + h2], pf[kt], vf[kt][ge] + 2 * h2);
    }

#pragma unroll
    for (int hf = 0; hf < 2; hf++) {
        float v = lsum[hf];
        v += __shfl_xor_sync(0xffffffffu, v, 1);
        v += __shfl_xor_sync(0xffffffffu, v, 2);
        lsum[hf] = 1.0f / v;
    }

    int b = bi / HWD;
    int sidx = bi - b * HWD;
    int hcol = h * HDIM;

    if (branch == 0) {
        // ---- coalesced store: stage O (160 s x 32 e fp32) in smem at FK ----
        __syncthreads();   // all warps done reading FK/FV
#pragma unroll
        for (int hf = 0; hf < 2; hf++) {
            int s = prow + 8 * hf;
            float rl = lsum[hf];
#pragma unroll
            for (int j = 0; j < 4; j++) {
                int e0 = j * 8 + (lane & 3) * 2;
                float2 v2;
                v2.x = O[j][hf * 2 + 0] * rl;
                v2.y = O[j][hf * 2 + 1] * rl;
                *reinterpret_cast<float2*>(smem + FK + oswz(s, e0)) = v2;
            }
        }
        __syncthreads();
        // cooperative float4 stores: 1280 float4, 4 per thread
        size_t base = (size_t)b * OUTB + (size_t)hcol * PIX + (size_t)sidx * HWD;
#pragma unroll
        for (int i = 0; i < 4; i++) {
            int idx = tid + i * 320;
            int e = idx / 40;
            int s = (idx - e * 40) * 4;
            float4 v4;
            v4.x = *reinterpret_cast<float*>(smem + FK + oswz(s + 0, e));
            v4.y = *reinterpret_cast<float*>(smem + FK + oswz(s + 1, e));
            v4.z = *reinterpret_cast<float*>(smem + FK + oswz(s + 2, e));
            v4.w = *reinterpret_cast<float*>(smem + FK + oswz(s + 3, e));
            *reinterpret_cast<float4*>(out + base + (size_t)e * PIX + s) = v4;
        }
    } else {
#pragma unroll
        for (int hf = 0; hf < 2; hf++) {
            int s = prow + 8 * hf;
            float rl = lsum[hf];
            size_t obase = (size_t)(BATCH + b) * OUTB + (size_t)hcol * PIX
                         + (size_t)s * HWD + sidx;
#pragma unroll
            for (int j = 0; j < 4; j++) {
#pragma unroll
                for (int b2 = 0; b2 < 2; b2++) {
                    int e = j * 8 + (lane & 3) * 2 + b2;
                    out[obase + (size_t)e * PIX] = O[j][hf * 2 + b2] * rl;
                }
            }
        }
    }
}

// ---------------- launch ----------------------------------------------------------
extern "C" void kernel_launch(void* const* d_in, const int* in_sizes, int n_in,
                              void* d_out, int out_size)
{
    const float* x      = (const float*)d_in[0];
    const float* ln_g   = (const float*)d_in[1];
    const float* ln_b   = (const float*)d_in[2];
    const float* conv_w = (const float*)d_in[3];
    const float* conv_b = (const float*)d_in[4];
    const float* wqh = (const float*)d_in[5];
    const float* bqh = (const float*)d_in[6];
    const float* wkh = (const float*)d_in[7];
    const float* bkh = (const float*)d_in[8];
    const float* wvh = (const float*)d_in[9];
    const float* bvh = (const float*)d_in[10];
    const float* wqv = (const float*)d_in[11];
    const float* bqv = (const float*)d_in[12];
    const float* wkv = (const float*)d_in[13];
    const float* bkv = (const float*)d_in[14];
    const float* wvv = (const float*)d_in[15];
    const float* bvv = (const float*)d_in[16];
    float* out = (float*)d_out;

    cudaFuncSetAttribute(conv_gemm_mma, cudaFuncAttributeMaxDynamicSharedMemorySize, GEMM_SMEM);
    cudaFuncSetAttribute(fused_qkv_attn, cudaFuncAttributeMaxDynamicSharedMemorySize, FUSED_SMEM);

    ln_fused_kernel<<<MTOK / 32, 256>>>(x, ln_g, ln_b);
    wconv_kernel<<<(CCH * CCH + 6 * DD * DD + 255) / 256, 256>>>(
        conv_w, wqh, wkh, wvh, wqv, wkv, wvv);

    conv_gemm_mma<<<dim3(2, MTOK / 64), 256, GEMM_SMEM>>>(conv_b);

    fused_qkv_attn<<<dim3(NHEADS, BATCH * HWD, 2), 320, FUSED_SMEM>>>(
        out, bqh, bkh, bvh, bqv, bkv, bvv);
}

// round 16
// speedup vs baseline: 1.0571x; 1.0571x over previous
#include <cuda_runtime.h>
#include <cuda_fp16.h>
#include <cstdint>

#define BATCH   8
#define CCH     320
#define HWD     160
#define DD      160
#define NHEADS  5
#define HDIM    32
#define PIX     (HWD*HWD)
#define MTOK    (BATCH*PIX)
#define OUTB    (HWD*HWD*HWD)
#define QK_SCALE 0.17677669529663687f

// ---------------- scratch ----------------------------------------------------
__device__ __half g_xn[(size_t)MTOK * CCH];      // LN output, fp16
__device__ __half g_y[2][(size_t)MTOK * DD];     // [0]=yh, [1]=yv permuted (fp16)
__device__ __half g_wc_f[(size_t)CCH * CCH];
__device__ __half g_wq_f[6][(size_t)DD * DD];

// ---------------- PTX helpers --------------------------------------------------
__device__ __forceinline__ uint32_t smem_u32(const void* p) {
    uint32_t a;
    asm("{ .reg .u64 t; cvta.to.shared.u64 t, %1; cvt.u32.u64 %0, t; }"
        : "=r"(a) : "l"(p));
    return a;
}
__device__ __forceinline__ void cp16(uint32_t dst, const void* src) {
    asm volatile("cp.async.cg.shared.global [%0], [%1], 16;"
                 :: "r"(dst), "l"(src) : "memory");
}
#define CP_COMMIT() asm volatile("cp.async.commit_group;" ::: "memory")
#define CP_WAIT(n)  asm volatile("cp.async.wait_group %0;" :: "n"(n) : "memory")

__device__ __forceinline__ void ldm_x4(uint32_t* r, uint32_t addr) {
    asm volatile("ldmatrix.sync.aligned.m8n8.x4.shared.b16 {%0,%1,%2,%3}, [%4];"
        : "=r"(r[0]), "=r"(r[1]), "=r"(r[2]), "=r"(r[3]) : "r"(addr));
}
__device__ __forceinline__ void ldm_x4_t(uint32_t* r, uint32_t addr) {
    asm volatile("ldmatrix.sync.aligned.m8n8.x4.trans.shared.b16 {%0,%1,%2,%3}, [%4];"
        : "=r"(r[0]), "=r"(r[1]), "=r"(r[2]), "=r"(r[3]) : "r"(addr));
}
__device__ __forceinline__ void mma_f16(float* d, const uint32_t* a, const uint32_t* b) {
    asm volatile(
        "mma.sync.aligned.m16n8k16.row.col.f32.f16.f16.f32 "
        "{%0,%1,%2,%3}, {%4,%5,%6,%7}, {%8,%9}, {%0,%1,%2,%3};"
        : "+f"(d[0]), "+f"(d[1]), "+f"(d[2]), "+f"(d[3])
        : "r"(a[0]), "r"(a[1]), "r"(a[2]), "r"(a[3]), "r"(b[0]), "r"(b[1]));
}

// 64B-row XOR swizzle (fp16 tiles)
__device__ __forceinline__ uint32_t swz(uint32_t row, uint32_t unit) {
    return row * 64u + ((unit ^ ((row >> 1) & 3u)) << 4);
}
__device__ __forceinline__ uint32_t hf2u(float a, float b) {
    __half2 t = __floats2half2_rn(a, b);
    return *reinterpret_cast<uint32_t*>(&t);
}

// ---------------- kernel 1: fused LN (stats + normalize + fp16) -----------------
__global__ __launch_bounds__(256) void ln_fused_kernel(
    const float* __restrict__ x, const float* __restrict__ lng,
    const float* __restrict__ lnb)
{
    __shared__ float s[CCH][33];
    __shared__ float ps1[8][32], ps2[8][32];
    __shared__ float mu_s[32], rs_s[32];
    int tok0 = blockIdx.x * 32;
    int b = tok0 / PIX;
    int pix0 = tok0 - b * PIX;
    int tid = threadIdx.x;
    const float* xb = x + (size_t)b * CCH * PIX + pix0;

#pragma unroll
    for (int i = 0; i < 40; i++) {
        int idx = tid + i * 256;
        int c = idx >> 5, t = idx & 31;
        s[c][t] = xb[(size_t)c * PIX + t];
    }
    __syncthreads();

    {
        int t = tid & 31, part = tid >> 5;
        float s1 = 0.f, s2 = 0.f;
#pragma unroll
        for (int i = 0; i < 40; i++) {
            float v = s[part * 40 + i][t];
            s1 += v; s2 += v * v;
        }
        ps1[part][t] = s1; ps2[part][t] = s2;
    }
    __syncthreads();
    if (tid < 32) {
        float a1 = 0.f, a2 = 0.f;
#pragma unroll
        for (int p = 0; p < 8; p++) { a1 += ps1[p][tid]; a2 += ps2[p][tid]; }
        float mu = a1 * (1.0f / CCH);
        mu_s[tid] = mu;
        rs_s[tid] = rsqrtf(a2 * (1.0f / CCH) - mu * mu + 1e-5f);
    }
    __syncthreads();

    int w = tid >> 5, lane = tid & 31;
#pragma unroll
    for (int i = 0; i < 4; i++) {
        int tt = w + 8 * i;
        int m = tok0 + tt;
        float mu = mu_s[tt], rs = rs_s[tt];
#pragma unroll
        for (int j = 0; j < 5; j++) {
            int c = lane * 2 + 64 * j;
            float v0 = (s[c][tt]     - mu) * rs * lng[c]     + lnb[c];
            float v1 = (s[c + 1][tt] - mu) * rs * lng[c + 1] + lnb[c + 1];
            *reinterpret_cast<uint32_t*>(&g_xn[(size_t)m * CCH + c]) = hf2u(v0, v1);
        }
    }
}

// ---------------- kernel 2: weights to fp16 -------------------------------------
__global__ __launch_bounds__(256) void wconv_kernel(
    const float* __restrict__ cw,
    const float* __restrict__ w0, const float* __restrict__ w1,
    const float* __restrict__ w2, const float* __restrict__ w3,
    const float* __restrict__ w4, const float* __restrict__ w5)
{
    int i = blockIdx.x * 256 + threadIdx.x;
    if (i < CCH * CCH) {
        g_wc_f[i] = __float2half_rn(cw[i]);
    } else {
        int j = i - CCH * CCH;
        if (j < 6 * DD * DD) {
            int z = j / (DD * DD);
            int rem = j - z * (DD * DD);
            const float* ws = (z == 0) ? w0 : (z == 1) ? w1 : (z == 2) ? w2
                             : (z == 3) ? w3 : (z == 4) ? w4 : w5;
            g_wq_f[z][rem] = __float2half_rn(ws[rem]);
        }
    }
}

// ---------------- conv GEMM (pipelined, unchanged) --------------------------------
#define STG_B  4096
#define STG_SZ 14336
#define GEMM_SMEM (4 * STG_SZ)

__device__ __forceinline__ void stage_load(uint32_t st,
    const __half* A, int astride, const __half* B, int bstride, int k0)
{
    int tid = threadIdx.x;
#pragma unroll
    for (int i = 0; i < 4; i++) {
        int idx = tid + i * 256;
        if (idx < 256) {
            int r = idx >> 2;
            int u = idx & 3;
            cp16(st + swz(r, u), A + (size_t)r * astride + k0 + u * 8);
        } else if (idx < 896) {
            int j = idx - 256;
            int r = j >> 2;
            int u = j & 3;
            cp16(st + STG_B + swz(r, u), B + (size_t)r * bstride + k0 + u * 8);
        }
    }
}

__device__ __forceinline__ void stage_compute(uint32_t st, int lane, int wm, int wn,
                                              float acc[10][4])
{
    uint32_t af[2][4];
    int arow = wm * 16 + (lane & 15);
#pragma unroll
    for (int ks = 0; ks < 2; ks++)
        ldm_x4(af[ks], st + swz(arow, (lane >> 4) + 2 * ks));
#pragma unroll
    for (int g = 0; g < 5; g++) {
        int brow = wn * 80 + g * 16 + (lane & 7) + ((lane >> 4) << 3);
        int bu = (lane >> 3) & 1;
#pragma unroll
        for (int ks = 0; ks < 2; ks++) {
            uint32_t bf[4];
            ldm_x4(bf, st + STG_B + swz(brow, bu + 2 * ks));
#pragma unroll
            for (int h2 = 0; h2 < 2; h2++)
                mma_f16(acc[g * 2 + h2], af[ks], bf + 2 * h2);
        }
    }
}

__global__ void __launch_bounds__(256, 2) conv_gemm_mma(const float* __restrict__ bias)
{
    extern __shared__ __align__(128) char smem[];
    uint32_t sb = smem_u32(smem);
    int ntile = blockIdx.x;
    int m0 = blockIdx.y * 64;
    int lane = threadIdx.x & 31;
    int wm = (threadIdx.x >> 5) & 3;
    int wn = threadIdx.x >> 7;
    const __half* A = g_xn + (size_t)m0 * CCH;
    const __half* B = g_wc_f + (size_t)(ntile * 160) * CCH;

    float acc[10][4];
#pragma unroll
    for (int a = 0; a < 10; a++)
#pragma unroll
        for (int c = 0; c < 4; c++) acc[a][c] = 0.f;

#pragma unroll
    for (int p = 0; p < 3; p++) {
        stage_load(sb + p * STG_SZ, A, CCH, B, CCH, p * 32);
        CP_COMMIT();
    }
    for (int c = 0; c < 10; c++) {
        if (c + 3 < 10) { CP_WAIT(2); } else { CP_WAIT(0); }
        __syncthreads();
        if (c + 3 < 10) {
            stage_load(sb + ((c + 3) & 3) * STG_SZ, A, CCH, B, CCH, (c + 3) * 32);
            CP_COMMIT();
        }
        stage_compute(sb + (c & 3) * STG_SZ, lane, wm, wn, acc);
    }

#pragma unroll
    for (int hf = 0; hf < 2; hf++) {
        int m = m0 + wm * 16 + (lane >> 2) + 8 * hf;
        size_t drow;
        if (ntile == 0) drow = (size_t)m;
        else {
            int b = m / PIX; int rem = m - b * PIX;
            int hh = rem / HWD; int ww = rem - hh * HWD;
            drow = ((size_t)b * HWD + ww) * HWD + hh;
        }
        __half* dh = g_y[ntile] + drow * DD;
#pragma unroll
        for (int j = 0; j < 10; j++) {
            int col = wn * 80 + j * 8 + (lane & 3) * 2;
            float v0 = acc[j][hf * 2 + 0] + bias[ntile * 160 + col];
            float v1 = acc[j][hf * 2 + 1] + bias[ntile * 160 + col + 1];
            *reinterpret_cast<uint32_t*>(dh + col) = hf2u(v0, v1);
        }
    }
}

// ---------------- kernel 3: FUSED qkv + attention ---------------------------------
// CTA = (head, sequence, branch). 320 threads = 10 warps, each owns 16 query rows.
// smem (100KB): Y 5 planes 50K | Wq,Wk,Wv 3x10K | k 10K | v 10K.
// All 3 projection GEMMs merged (shared A frags, 3 accumulators). q/P in regs.
// Direct stores (R14 epilogue — branch 0 is already sector-full).
#define FY   0
#define FW   51200
#define FK   81920
#define FV   92160
#define FUSED_SMEM 102400

__global__ void __launch_bounds__(320, 2) fused_qkv_attn(
    float* __restrict__ out,
    const float* __restrict__ bq_h, const float* __restrict__ bk_h,
    const float* __restrict__ bv_h, const float* __restrict__ bq_v,
    const float* __restrict__ bk_v, const float* __restrict__ bv_v)
{
    extern __shared__ __align__(128) char smem[];
    uint32_t sb = smem_u32(smem);
    int h      = blockIdx.x;          // head (fastest -> L2 reuse of Y)
    int bi     = blockIdx.y;          // sequence
    int branch = blockIdx.z;
    int tid = threadIdx.x, lane = tid & 31, w = tid >> 5;   // w: 0..9
    size_t seqBase = (size_t)bi * HWD;
    int z0 = branch * 3;

    const __half* ybase = &g_y[branch][seqBase * DD];
    const __half* wsrc[3] = {
        &g_wq_f[z0 + 0][(size_t)h * HDIM * DD],
        &g_wq_f[z0 + 1][(size_t)h * HDIM * DD],
        &g_wq_f[z0 + 2][(size_t)h * HDIM * DD]};
    const float* bq = (branch ? bq_v : bq_h) + h * HDIM;
    const float* bk = (branch ? bk_v : bk_h) + h * HDIM;
    const float* bv = (branch ? bv_v : bv_h) + h * HDIM;

    // ---- prologue: Y (3200 cp16, 5 planes) + all W (1920 cp16), one group ----
#pragma unroll
    for (int i = 0; i < 10; i++) {
        int idx = tid + i * 320;
        int plane = idx / 640;
        int rem = idx - plane * 640;
        int r = rem >> 2, u = rem & 3;
        cp16(sb + FY + plane * 10240 + swz(r, u),
             ybase + (size_t)r * DD + plane * 32 + u * 8);
    }
#pragma unroll
    for (int i = 0; i < 6; i++) {
        int idx = tid + i * 320;
        int g = idx / 640;
        int rem = idx - g * 640;
        int plane = rem >> 7;
        int rr = rem & 127;
        int r = rr >> 2, u = rr & 3;
        cp16(sb + FW + g * 10240 + plane * 2048 + swz(r, u),
             wsrc[g] + (size_t)r * DD + plane * 32 + u * 8);
    }
    CP_COMMIT();
    CP_WAIT(0);
    __syncthreads();                 // barrier #1

    int arow = w * 16 + (lane & 15);
    int au   = (lane >> 4);
    int prow = w * 16 + (lane >> 2);
    uint32_t brow_b = (lane & 7) + ((lane >> 4) << 3);
    uint32_t bu = (lane >> 3) & 1;

    // ---- merged q+k+v GEMMs (shared A frags, 3 accumulators) ----
    uint32_t qf[2][4];
    {
        float accq[4][4], acck[4][4], accv[4][4];
#pragma unroll
        for (int a = 0; a < 4; a++)
#pragma unroll
            for (int e = 0; e < 4; e++) {
                accq[a][e] = 0.f; acck[a][e] = 0.f; accv[a][e] = 0.f;
            }

#pragma unroll
        for (int c = 0; c < 5; c++) {
            uint32_t af[2][4];
#pragma unroll
            for (int ke = 0; ke < 2; ke++)
                ldm_x4(af[ke], sb + FY + c * 10240 + swz(arow, au + 2 * ke));
#pragma unroll
            for (int g2 = 0; g2 < 2; g2++) {
                uint32_t brow = g2 * 16 + brow_b;
#pragma unroll
                for (int ke = 0; ke < 2; ke++) {
                    uint32_t bfq[4], bfk[4], bfv[4];
                    ldm_x4(bfq, sb + FW + 0 * 10240 + c * 2048 + swz(brow, bu + 2 * ke));
                    ldm_x4(bfk, sb + FW + 1 * 10240 + c * 2048 + swz(brow, bu + 2 * ke));
                    ldm_x4(bfv, sb + FW + 2 * 10240 + c * 2048 + swz(brow, bu + 2 * ke));
#pragma unroll
                    for (int h2 = 0; h2 < 2; h2++) {
                        mma_f16(accq[g2 * 2 + h2], af[ke], bfq + 2 * h2);
                        mma_f16(acck[g2 * 2 + h2], af[ke], bfk + 2 * h2);
                        mma_f16(accv[g2 * 2 + h2], af[ke], bfv + 2 * h2);
                    }
                }
            }
        }

        // k, v -> smem planes (warp-private rows)
#pragma unroll
        for (int j = 0; j < 4; j++) {
            int n0 = j * 8 + (lane & 3) * 2;
            float bk0 = bk[n0], bk1 = bk[n0 + 1];
            float bv0 = bv[n0], bv1 = bv[n0 + 1];
#pragma unroll
            for (int hf = 0; hf < 2; hf++) {
                uint32_t off = swz(prow + 8 * hf, j) + (lane & 3) * 4;
                *reinterpret_cast<uint32_t*>(smem + FK + off) =
                    hf2u(acck[j][hf * 2 + 0] + bk0, acck[j][hf * 2 + 1] + bk1);
                *reinterpret_cast<uint32_t*>(smem + FV + off) =
                    hf2u(accv[j][hf * 2 + 0] + bv0, accv[j][hf * 2 + 1] + bv1);
            }
        }

        // q -> register A-fragments (bias + QK_SCALE folded)
        int c2 = (lane & 3) * 2;
#pragma unroll
        for (int ke = 0; ke < 2; ke++) {
            float blo0 = bq[16 * ke + c2],     blo1 = bq[16 * ke + c2 + 1];
            float bhi0 = bq[16 * ke + 8 + c2], bhi1 = bq[16 * ke + 8 + c2 + 1];
            qf[ke][0] = hf2u((accq[2 * ke][0] + blo0) * QK_SCALE,
                             (accq[2 * ke][1] + blo1) * QK_SCALE);
            qf[ke][1] = hf2u((accq[2 * ke][2] + blo0) * QK_SCALE,
                             (accq[2 * ke][3] + blo1) * QK_SCALE);
            qf[ke][2] = hf2u((accq[2 * ke + 1][0] + bhi0) * QK_SCALE,
                             (accq[2 * ke + 1][1] + bhi1) * QK_SCALE);
            qf[ke][3] = hf2u((accq[2 * ke + 1][2] + bhi0) * QK_SCALE,
                             (accq[2 * ke + 1][3] + bhi1) * QK_SCALE);
        }
    }
    __syncthreads();                 // barrier #2: k,v planes visible

    // ---- attention: register q/P, smem K/V, V prefetched ahead of exp ----
    float O[4][4];
#pragma unroll
    for (int a = 0; a < 4; a++)
#pragma unroll
        for (int e = 0; e < 4; e++) O[a][e] = 0.f;
    float lsum[2] = {0.f, 0.f};

#pragma unroll
    for (int tb = 0; tb < 5; tb++) {
        int t0 = tb * 32;
        float S[4][4];
#pragma unroll
        for (int a = 0; a < 4; a++)
#pragma unroll
            for (int e = 0; e < 4; e++) S[a][e] = 0.f;

#pragma unroll
        for (int g = 0; g < 2; g++) {
            int brow = t0 + g * 16 + brow_b;
#pragma unroll
            for (int ke = 0; ke < 2; ke++) {
                uint32_t kf[4];
                ldm_x4(kf, sb + FK + swz(brow, bu + 2 * ke));
#pragma unroll
                for (int h2 = 0; h2 < 2; h2++)
                    mma_f16(S[g * 2 + h2], qf[ke], kf + 2 * h2);
            }
        }

        uint32_t vf[2][2][4];
#pragma unroll
        for (int kt = 0; kt < 2; kt++)
#pragma unroll
            for (int ge = 0; ge < 2; ge++) {
                int vrow = t0 + kt * 16 + (lane & 15);
                int vu = ge * 2 + (lane >> 4);
                ldm_x4_t(vf[kt][ge], sb + FV + swz(vrow, vu));
            }

        float P[4][4];
#pragma unroll
        for (int j = 0; j < 4; j++) {
            P[j][0] = __expf(S[j][0]);
            P[j][1] = __expf(S[j][1]);
            P[j][2] = __expf(S[j][2]);
            P[j][3] = __expf(S[j][3]);
            lsum[0] += P[j][0] + P[j][1];
            lsum[1] += P[j][2] + P[j][3];
        }
        uint32_t pf[2][4];
#pragma unroll
        for (int kt = 0; kt < 2; kt++) {
            pf[kt][0] = hf2u(P[2 * kt][0],     P[2 * kt][1]);
            pf[kt][1] = hf2u(P[2 * kt][2],     P[2 * kt][3]);
            pf[kt][2] = hf2u(P[2 * kt + 1][0], P[2 * kt + 1][1]);
            pf[kt][3] = hf2u(P[2 * kt + 1][2], P[2 * kt + 1][3]);
        }

#pragma unroll
        for (int kt = 0; kt < 2; kt++)
#pragma unroll
            for (int ge = 0; ge < 2; ge++)
#pragma unroll
                for (int h2 = 0; h2 < 2; h2++)
                    mma_f16(O[ge * 2 + h2], pf[kt], vf[kt][ge] + 2 * h2);
    }

#pragma unroll
    for (int hf = 0; hf < 2; hf++) {
        float v = lsum[hf];
        v += __shfl_xor_sync(0xffffffffu, v, 1);
        v += __shfl_xor_sync(0xffffffffu, v, 2);
        lsum[hf] = 1.0f / v;
    }

    int b = bi / HWD;
    int sidx = bi - b * HWD;
    int hcol = h * HDIM;
#pragma unroll
    for (int hf = 0; hf < 2; hf++) {
        int s = prow + 8 * hf;
        float rl = lsum[hf];
        size_t obase;
        if (branch == 0)
            obase = (size_t)b * OUTB + (size_t)hcol * PIX + (size_t)sidx * HWD + s;
        else
            obase = (size_t)(BATCH + b) * OUTB + (size_t)hcol * PIX + (size_t)s * HWD + sidx;
#pragma unroll
        for (int j = 0; j < 4; j++) {
#pragma unroll
            for (int b2 = 0; b2 < 2; b2++) {
                int e = j * 8 + (lane & 3) * 2 + b2;
                out[obase + (size_t)e * PIX] = O[j][hf * 2 + b2] * rl;
            }
        }
    }
}

// ---------------- launch ----------------------------------------------------------
extern "C" void kernel_launch(void* const* d_in, const int* in_sizes, int n_in,
                              void* d_out, int out_size)
{
    const float* x      = (const float*)d_in[0];
    const float* ln_g   = (const float*)d_in[1];
    const float* ln_b   = (const float*)d_in[2];
    const float* conv_w = (const float*)d_in[3];
    const float* conv_b = (const float*)d_in[4];
    const float* wqh = (const float*)d_in[5];
    const float* bqh = (const float*)d_in[6];
    const float* wkh = (const float*)d_in[7];
    const float* bkh = (const float*)d_in[8];
    const float* wvh = (const float*)d_in[9];
    const float* bvh = (const float*)d_in[10];
    const float* wqv = (const float*)d_in[11];
    const float* bqv = (const float*)d_in[12];
    const float* wkv = (const float*)d_in[13];
    const float* bkv = (const float*)d_in[14];
    const float* wvv = (const float*)d_in[15];
    const float* bvv = (const float*)d_in[16];
    float* out = (float*)d_out;

    cudaFuncSetAttribute(conv_gemm_mma, cudaFuncAttributeMaxDynamicSharedMemorySize, GEMM_SMEM);
    cudaFuncSetAttribute(fused_qkv_attn, cudaFuncAttributeMaxDynamicSharedMemorySize, FUSED_SMEM);

    ln_fused_kernel<<<MTOK / 32, 256>>>(x, ln_g, ln_b);
    wconv_kernel<<<(CCH * CCH + 6 * DD * DD + 255) / 256, 256>>>(
        conv_w, wqh, wkh, wvh, wqv, wkv, wvv);

    conv_gemm_mma<<<dim3(2, MTOK / 64), 256, GEMM_SMEM>>>(conv_b);

    fused_qkv_attn<<<dim3(NHEADS, BATCH * HWD, 2), 320, FUSED_SMEM>>>(
        out, bqh, bkh, bvh, bqv, bkv, bvv);
}

// round 17
// speedup vs baseline: 1.0601x; 1.0029x over previous
#include <cuda_runtime.h>
#include <cuda_fp16.h>
#include <cstdint>

#define BATCH   8
#define CCH     320
#define HWD     160
#define DD      160
#define NHEADS  5
#define HDIM    32
#define PIX     (HWD*HWD)
#define MTOK    (BATCH*PIX)
#define OUTB    (HWD*HWD*HWD)
#define QK_SCALE 0.17677669529663687f
// QK_SCALE * log2(e): logits pre-scaled for exp2f
#define QK_SCALE_L2E 0.25505000370581073f

// ---------------- scratch ----------------------------------------------------
__device__ __half g_xn[(size_t)MTOK * CCH];      // LN output, fp16
__device__ __half g_y[2][(size_t)MTOK * DD];     // [0]=yh, [1]=yv permuted (fp16)
__device__ __half g_wc_f[(size_t)CCH * CCH];
__device__ __half g_wq_f[6][(size_t)DD * DD];

// ---------------- PTX helpers --------------------------------------------------
__device__ __forceinline__ uint32_t smem_u32(const void* p) {
    uint32_t a;
    asm("{ .reg .u64 t; cvta.to.shared.u64 t, %1; cvt.u32.u64 %0, t; }"
        : "=r"(a) : "l"(p));
    return a;
}
__device__ __forceinline__ void cp16(uint32_t dst, const void* src) {
    asm volatile("cp.async.cg.shared.global [%0], [%1], 16;"
                 :: "r"(dst), "l"(src) : "memory");
}
#define CP_COMMIT() asm volatile("cp.async.commit_group;" ::: "memory")
#define CP_WAIT(n)  asm volatile("cp.async.wait_group %0;" :: "n"(n) : "memory")

__device__ __forceinline__ void ldm_x4(uint32_t* r, uint32_t addr) {
    asm volatile("ldmatrix.sync.aligned.m8n8.x4.shared.b16 {%0,%1,%2,%3}, [%4];"
        : "=r"(r[0]), "=r"(r[1]), "=r"(r[2]), "=r"(r[3]) : "r"(addr));
}
__device__ __forceinline__ void ldm_x4_t(uint32_t* r, uint32_t addr) {
    asm volatile("ldmatrix.sync.aligned.m8n8.x4.trans.shared.b16 {%0,%1,%2,%3}, [%4];"
        : "=r"(r[0]), "=r"(r[1]), "=r"(r[2]), "=r"(r[3]) : "r"(addr));
}
__device__ __forceinline__ void mma_f16(float* d, const uint32_t* a, const uint32_t* b) {
    asm volatile(
        "mma.sync.aligned.m16n8k16.row.col.f32.f16.f16.f32 "
        "{%0,%1,%2,%3}, {%4,%5,%6,%7}, {%8,%9}, {%0,%1,%2,%3};"
        : "+f"(d[0]), "+f"(d[1]), "+f"(d[2]), "+f"(d[3])
        : "r"(a[0]), "r"(a[1]), "r"(a[2]), "r"(a[3]), "r"(b[0]), "r"(b[1]));
}

// 64B-row XOR swizzle (fp16 tiles)
__device__ __forceinline__ uint32_t swz(uint32_t row, uint32_t unit) {
    return row * 64u + ((unit ^ ((row >> 1) & 3u)) << 4);
}
__device__ __forceinline__ uint32_t hf2u(float a, float b) {
    __half2 t = __floats2half2_rn(a, b);
    return *reinterpret_cast<uint32_t*>(&t);
}

// ---------------- kernel 1: fused LN (stats + normalize + fp16) -----------------
__global__ __launch_bounds__(256) void ln_fused_kernel(
    const float* __restrict__ x, const float* __restrict__ lng,
    const float* __restrict__ lnb)
{
    __shared__ float s[CCH][33];
    __shared__ float ps1[8][32], ps2[8][32];
    __shared__ float mu_s[32], rs_s[32];
    int tok0 = blockIdx.x * 32;
    int b = tok0 / PIX;
    int pix0 = tok0 - b * PIX;
    int tid = threadIdx.x;
    const float* xb = x + (size_t)b * CCH * PIX + pix0;

#pragma unroll
    for (int i = 0; i < 40; i++) {
        int idx = tid + i * 256;
        int c = idx >> 5, t = idx & 31;
        s[c][t] = xb[(size_t)c * PIX + t];
    }
    __syncthreads();

    {
        int t = tid & 31, part = tid >> 5;
        float s1 = 0.f, s2 = 0.f;
#pragma unroll
        for (int i = 0; i < 40; i++) {
            float v = s[part * 40 + i][t];
            s1 += v; s2 += v * v;
        }
        ps1[part][t] = s1; ps2[part][t] = s2;
    }
    __syncthreads();
    if (tid < 32) {
        float a1 = 0.f, a2 = 0.f;
#pragma unroll
        for (int p = 0; p < 8; p++) { a1 += ps1[p][tid]; a2 += ps2[p][tid]; }
        float mu = a1 * (1.0f / CCH);
        mu_s[tid] = mu;
        rs_s[tid] = rsqrtf(a2 * (1.0f / CCH) - mu * mu + 1e-5f);
    }
    __syncthreads();

    int w = tid >> 5, lane = tid & 31;
#pragma unroll
    for (int i = 0; i < 4; i++) {
        int tt = w + 8 * i;
        int m = tok0 + tt;
        float mu = mu_s[tt], rs = rs_s[tt];
#pragma unroll
        for (int j = 0; j < 5; j++) {
            int c = lane * 2 + 64 * j;
            float v0 = (s[c][tt]     - mu) * rs * lng[c]     + lnb[c];
            float v1 = (s[c + 1][tt] - mu) * rs * lng[c + 1] + lnb[c + 1];
            *reinterpret_cast<uint32_t*>(&g_xn[(size_t)m * CCH + c]) = hf2u(v0, v1);
        }
    }
}

// ---------------- kernel 2: weights to fp16 -------------------------------------
__global__ __launch_bounds__(256) void wconv_kernel(
    const float* __restrict__ cw,
    const float* __restrict__ w0, const float* __restrict__ w1,
    const float* __restrict__ w2, const float* __restrict__ w3,
    const float* __restrict__ w4, const float* __restrict__ w5)
{
    int i = blockIdx.x * 256 + threadIdx.x;
    if (i < CCH * CCH) {
        g_wc_f[i] = __float2half_rn(cw[i]);
    } else {
        int j = i - CCH * CCH;
        if (j < 6 * DD * DD) {
            int z = j / (DD * DD);
            int rem = j - z * (DD * DD);
            const float* ws = (z == 0) ? w0 : (z == 1) ? w1 : (z == 2) ? w2
                             : (z == 3) ? w3 : (z == 4) ? w4 : w5;
            g_wq_f[z][rem] = __float2half_rn(ws[rem]);
        }
    }
}

// ---------------- conv GEMM (pipelined, unchanged) --------------------------------
#define STG_B  4096
#define STG_SZ 14336
#define GEMM_SMEM (4 * STG_SZ)

__device__ __forceinline__ void stage_load(uint32_t st,
    const __half* A, int astride, const __half* B, int bstride, int k0)
{
    int tid = threadIdx.x;
#pragma unroll
    for (int i = 0; i < 4; i++) {
        int idx = tid + i * 256;
        if (idx < 256) {
            int r = idx >> 2;
            int u = idx & 3;
            cp16(st + swz(r, u), A + (size_t)r * astride + k0 + u * 8);
        } else if (idx < 896) {
            int j = idx - 256;
            int r = j >> 2;
            int u = j & 3;
            cp16(st + STG_B + swz(r, u), B + (size_t)r * bstride + k0 + u * 8);
        }
    }
}

__device__ __forceinline__ void stage_compute(uint32_t st, int lane, int wm, int wn,
                                              float acc[10][4])
{
    uint32_t af[2][4];
    int arow = wm * 16 + (lane & 15);
#pragma unroll
    for (int ks = 0; ks < 2; ks++)
        ldm_x4(af[ks], st + swz(arow, (lane >> 4) + 2 * ks));
#pragma unroll
    for (int g = 0; g < 5; g++) {
        int brow = wn * 80 + g * 16 + (lane & 7) + ((lane >> 4) << 3);
        int bu = (lane >> 3) & 1;
#pragma unroll
        for (int ks = 0; ks < 2; ks++) {
            uint32_t bf[4];
            ldm_x4(bf, st + STG_B + swz(brow, bu + 2 * ks));
#pragma unroll
            for (int h2 = 0; h2 < 2; h2++)
                mma_f16(acc[g * 2 + h2], af[ks], bf + 2 * h2);
        }
    }
}

__global__ void __launch_bounds__(256, 2) conv_gemm_mma(const float* __restrict__ bias)
{
    extern __shared__ __align__(128) char smem[];
    uint32_t sb = smem_u32(smem);
    int ntile = blockIdx.x;
    int m0 = blockIdx.y * 64;
    int lane = threadIdx.x & 31;
    int wm = (threadIdx.x >> 5) & 3;
    int wn = threadIdx.x >> 7;
    const __half* A = g_xn + (size_t)m0 * CCH;
    const __half* B = g_wc_f + (size_t)(ntile * 160) * CCH;

    float acc[10][4];
#pragma unroll
    for (int a = 0; a < 10; a++)
#pragma unroll
        for (int c = 0; c < 4; c++) acc[a][c] = 0.f;

#pragma unroll
    for (int p = 0; p < 3; p++) {
        stage_load(sb + p * STG_SZ, A, CCH, B, CCH, p * 32);
        CP_COMMIT();
    }
    for (int c = 0; c < 10; c++) {
        if (c + 3 < 10) { CP_WAIT(2); } else { CP_WAIT(0); }
        __syncthreads();
        if (c + 3 < 10) {
            stage_load(sb + ((c + 3) & 3) * STG_SZ, A, CCH, B, CCH, (c + 3) * 32);
            CP_COMMIT();
        }
        stage_compute(sb + (c & 3) * STG_SZ, lane, wm, wn, acc);
    }

#pragma unroll
    for (int hf = 0; hf < 2; hf++) {
        int m = m0 + wm * 16 + (lane >> 2) + 8 * hf;
        size_t drow;
        if (ntile == 0) drow = (size_t)m;
        else {
            int b = m / PIX; int rem = m - b * PIX;
            int hh = rem / HWD; int ww = rem - hh * HWD;
            drow = ((size_t)b * HWD + ww) * HWD + hh;
        }
        __half* dh = g_y[ntile] + drow * DD;
#pragma unroll
        for (int j = 0; j < 10; j++) {
            int col = wn * 80 + j * 8 + (lane & 3) * 2;
            float v0 = acc[j][hf * 2 + 0] + bias[ntile * 160 + col];
            float v1 = acc[j][hf * 2 + 1] + bias[ntile * 160 + col + 1];
            *reinterpret_cast<uint32_t*>(dh + col) = hf2u(v0, v1);
        }
    }
}

// ---------------- kernel 3: FUSED qkv + attention ---------------------------------
// CTA = (head, sequence, branch). 320 threads = 10 warps, each owns 16 query rows.
// smem (100KB): Y 5 planes 50K | Wq,Wk,Wv 3x10K | k 10K | v 10K.
// Merged q+k+v GEMMs; q/P in registers; incremental prologue waits (compute
// starts after W+Y0 arrive); exp2f with folded log2e scale.
#define FY   0
#define FW   51200
#define FK   81920
#define FV   92160
#define FUSED_SMEM 102400

__global__ void __launch_bounds__(320, 2) fused_qkv_attn(
    float* __restrict__ out,
    const float* __restrict__ bq_h, const float* __restrict__ bk_h,
    const float* __restrict__ bv_h, const float* __restrict__ bq_v,
    const float* __restrict__ bk_v, const float* __restrict__ bv_v)
{
    extern __shared__ __align__(128) char smem[];
    uint32_t sb = smem_u32(smem);
    int h      = blockIdx.x;          // head (fastest -> L2 reuse of Y)
    int bi     = blockIdx.y;          // sequence
    int branch = blockIdx.z;
    int tid = threadIdx.x, lane = tid & 31, w = tid >> 5;   // w: 0..9
    size_t seqBase = (size_t)bi * HWD;
    int z0 = branch * 3;

    const __half* ybase = &g_y[branch][seqBase * DD];
    const __half* wsrc[3] = {
        &g_wq_f[z0 + 0][(size_t)h * HDIM * DD],
        &g_wq_f[z0 + 1][(size_t)h * HDIM * DD],
        &g_wq_f[z0 + 2][(size_t)h * HDIM * DD]};
    const float* bq = (branch ? bq_v : bq_h) + h * HDIM;
    const float* bk = (branch ? bk_v : bk_h) + h * HDIM;
    const float* bv = (branch ? bv_v : bv_h) + h * HDIM;

    // ---- prologue: group0 = {all W + Y plane 0}; groups 1..4 = Y planes 1..4 ----
    // W: 1920 cp16 over 320 threads = 6 each
#pragma unroll
    for (int i = 0; i < 6; i++) {
        int idx = tid + i * 320;
        int g = idx / 640;
        int rem = idx - g * 640;
        int plane = rem >> 7;
        int rr = rem & 127;
        int r = rr >> 2, u = rr & 3;
        cp16(sb + FW + g * 10240 + plane * 2048 + swz(r, u),
             wsrc[g] + (size_t)r * DD + plane * 32 + u * 8);
    }
    // Y plane 0: 640 cp16 = 2 each
#pragma unroll
    for (int i = 0; i < 2; i++) {
        int idx = tid + i * 320;
        int r = idx >> 2, u = idx & 3;
        cp16(sb + FY + swz(r, u), ybase + (size_t)r * DD + u * 8);
    }
    CP_COMMIT();
    // Y planes 1..4, one group each
#pragma unroll
    for (int p = 1; p < 5; p++) {
#pragma unroll
        for (int i = 0; i < 2; i++) {
            int idx = tid + i * 320;
            int r = idx >> 2, u = idx & 3;
            cp16(sb + FY + p * 10240 + swz(r, u),
                 ybase + (size_t)r * DD + p * 32 + u * 8);
        }
        CP_COMMIT();
    }

    int arow = w * 16 + (lane & 15);
    int au   = (lane >> 4);
    int prow = w * 16 + (lane >> 2);
    uint32_t brow_b = (lane & 7) + ((lane >> 4) << 3);
    uint32_t bu = (lane >> 3) & 1;

    // ---- merged q+k+v GEMMs with incremental chunk waits ----
    uint32_t qf[2][4];
    {
        float accq[4][4], acck[4][4], accv[4][4];
#pragma unroll
        for (int a = 0; a < 4; a++)
#pragma unroll
            for (int e = 0; e < 4; e++) {
                accq[a][e] = 0.f; acck[a][e] = 0.f; accv[a][e] = 0.f;
            }

#pragma unroll
        for (int c = 0; c < 5; c++) {
            if (c == 0)      { CP_WAIT(4); }
            else if (c == 1) { CP_WAIT(3); }
            else if (c == 2) { CP_WAIT(2); }
            else if (c == 3) { CP_WAIT(1); }
            else             { CP_WAIT(0); }
            __syncthreads();          // chunk c (and W for c=0) visible

            uint32_t af[2][4];
#pragma unroll
            for (int ke = 0; ke < 2; ke++)
                ldm_x4(af[ke], sb + FY + c * 10240 + swz(arow, au + 2 * ke));
#pragma unroll
            for (int g2 = 0; g2 < 2; g2++) {
                uint32_t brow = g2 * 16 + brow_b;
#pragma unroll
                for (int ke = 0; ke < 2; ke++) {
                    uint32_t bfq[4], bfk[4], bfv[4];
                    ldm_x4(bfq, sb + FW + 0 * 10240 + c * 2048 + swz(brow, bu + 2 * ke));
                    ldm_x4(bfk, sb + FW + 1 * 10240 + c * 2048 + swz(brow, bu + 2 * ke));
                    ldm_x4(bfv, sb + FW + 2 * 10240 + c * 2048 + swz(brow, bu + 2 * ke));
#pragma unroll
                    for (int h2 = 0; h2 < 2; h2++) {
                        mma_f16(accq[g2 * 2 + h2], af[ke], bfq + 2 * h2);
                        mma_f16(acck[g2 * 2 + h2], af[ke], bfk + 2 * h2);
                        mma_f16(accv[g2 * 2 + h2], af[ke], bfv + 2 * h2);
                    }
                }
            }
        }

        // k, v -> smem planes (warp-private rows)
#pragma unroll
        for (int j = 0; j < 4; j++) {
            int n0 = j * 8 + (lane & 3) * 2;
            float bk0 = bk[n0], bk1 = bk[n0 + 1];
            float bv0 = bv[n0], bv1 = bv[n0 + 1];
#pragma unroll
            for (int hf = 0; hf < 2; hf++) {
                uint32_t off = swz(prow + 8 * hf, j) + (lane & 3) * 4;
                *reinterpret_cast<uint32_t*>(smem + FK + off) =
                    hf2u(acck[j][hf * 2 + 0] + bk0, acck[j][hf * 2 + 1] + bk1);
                *reinterpret_cast<uint32_t*>(smem + FV + off) =
                    hf2u(accv[j][hf * 2 + 0] + bv0, accv[j][hf * 2 + 1] + bv1);
            }
        }

        // q -> register A-fragments (bias + QK_SCALE*log2e folded)
        int c2 = (lane & 3) * 2;
#pragma unroll
        for (int ke = 0; ke < 2; ke++) {
            float blo0 = bq[16 * ke + c2],     blo1 = bq[16 * ke + c2 + 1];
            float bhi0 = bq[16 * ke + 8 + c2], bhi1 = bq[16 * ke + 8 + c2 + 1];
            qf[ke][0] = hf2u((accq[2 * ke][0] + blo0) * QK_SCALE_L2E,
                             (accq[2 * ke][1] + blo1) * QK_SCALE_L2E);
            qf[ke][1] = hf2u((accq[2 * ke][2] + blo0) * QK_SCALE_L2E,
                             (accq[2 * ke][3] + blo1) * QK_SCALE_L2E);
            qf[ke][2] = hf2u((accq[2 * ke + 1][0] + bhi0) * QK_SCALE_L2E,
                             (accq[2 * ke + 1][1] + bhi1) * QK_SCALE_L2E);
            qf[ke][3] = hf2u((accq[2 * ke + 1][2] + bhi0) * QK_SCALE_L2E,
                             (accq[2 * ke + 1][3] + bhi1) * QK_SCALE_L2E);
        }
    }
    __syncthreads();                 // k,v planes visible

    // ---- attention: register q/P, smem K/V, V prefetched ahead of exp ----
    float O[4][4];
#pragma unroll
    for (int a = 0; a < 4; a++)
#pragma unroll
        for (int e = 0; e < 4; e++) O[a][e] = 0.f;
    float lsum[2] = {0.f, 0.f};

#pragma unroll
    for (int tb = 0; tb < 5; tb++) {
        int t0 = tb * 32;
        float S[4][4];
#pragma unroll
        for (int a = 0; a < 4; a++)
#pragma unroll
            for (int e = 0; e < 4; e++) S[a][e] = 0.f;

#pragma unroll
        for (int g = 0; g < 2; g++) {
            int brow = t0 + g * 16 + brow_b;
#pragma unroll
            for (int ke = 0; ke < 2; ke++) {
                uint32_t kf[4];
                ldm_x4(kf, sb + FK + swz(brow, bu + 2 * ke));
#pragma unroll
                for (int h2 = 0; h2 < 2; h2++)
                    mma_f16(S[g * 2 + h2], qf[ke], kf + 2 * h2);
            }
        }

        uint32_t vf[2][2][4];
#pragma unroll
        for (int kt = 0; kt < 2; kt++)
#pragma unroll
            for (int ge = 0; ge < 2; ge++) {
                int vrow = t0 + kt * 16 + (lane & 15);
                int vu = ge * 2 + (lane >> 4);
                ldm_x4_t(vf[kt][ge], sb + FV + swz(vrow, vu));
            }

        float P[4][4];
#pragma unroll
        for (int j = 0; j < 4; j++) {
            P[j][0] = exp2f(S[j][0]);
            P[j][1] = exp2f(S[j][1]);
            P[j][2] = exp2f(S[j][2]);
            P[j][3] = exp2f(S[j][3]);
            lsum[0] += P[j][0] + P[j][1];
            lsum[1] += P[j][2] + P[j][3];
        }
        uint32_t pf[2][4];
#pragma unroll
        for (int kt = 0; kt < 2; kt++) {
            pf[kt][0] = hf2u(P[2 * kt][0],     P[2 * kt][1]);
            pf[kt][1] = hf2u(P[2 * kt][2],     P[2 * kt][3]);
            pf[kt][2] = hf2u(P[2 * kt + 1][0], P[2 * kt + 1][1]);
            pf[kt][3] = hf2u(P[2 * kt + 1][2], P[2 * kt + 1][3]);
        }

#pragma unroll
        for (int kt = 0; kt < 2; kt++)
#pragma unroll
            for (int ge = 0; ge < 2; ge++)
#pragma unroll
                for (int h2 = 0; h2 < 2; h2++)
                    mma_f16(O[ge * 2 + h2], pf[kt], vf[kt][ge] + 2 * h2);
    }

#pragma unroll
    for (int hf = 0; hf < 2; hf++) {
        float v = lsum[hf];
        v += __shfl_xor_sync(0xffffffffu, v, 1);
        v += __shfl_xor_sync(0xffffffffu, v, 2);
        lsum[hf] = 1.0f / v;
    }

    int b = bi / HWD;
    int sidx = bi - b * HWD;
    int hcol = h * HDIM;
#pragma unroll
    for (int hf = 0; hf < 2; hf++) {
        int s = prow + 8 * hf;
        float rl = lsum[hf];
        size_t obase;
        if (branch == 0)
            obase = (size_t)b * OUTB + (size_t)hcol * PIX + (size_t)sidx * HWD + s;
        else
            obase = (size_t)(BATCH + b) * OUTB + (size_t)hcol * PIX + (size_t)s * HWD + sidx;
#pragma unroll
        for (int j = 0; j < 4; j++) {
#pragma unroll
            for (int b2 = 0; b2 < 2; b2++) {
                int e = j * 8 + (lane & 3) * 2 + b2;
                out[obase + (size_t)e * PIX] = O[j][hf * 2 + b2] * rl;
            }
        }
    }
}

// ---------------- launch ----------------------------------------------------------
extern "C" void kernel_launch(void* const* d_in, const int* in_sizes, int n_in,
                              void* d_out, int out_size)
{
    const float* x      = (const float*)d_in[0];
    const float* ln_g   = (const float*)d_in[1];
    const float* ln_b   = (const float*)d_in[2];
    const float* conv_w = (const float*)d_in[3];
    const float* conv_b = (const float*)d_in[4];
    const float* wqh = (const float*)d_in[5];
    const float* bqh = (const float*)d_in[6];
    const float* wkh = (const float*)d_in[7];
    const float* bkh = (const float*)d_in[8];
    const float* wvh = (const float*)d_in[9];
    const float* bvh = (const float*)d_in[10];
    const float* wqv = (const float*)d_in[11];
    const float* bqv = (const float*)d_in[12];
    const float* wkv = (const float*)d_in[13];
    const float* bkv = (const float*)d_in[14];
    const float* wvv = (const float*)d_in[15];
    const float* bvv = (const float*)d_in[16];
    float* out = (float*)d_out;

    cudaFuncSetAttribute(conv_gemm_mma, cudaFuncAttributeMaxDynamicSharedMemorySize, GEMM_SMEM);
    cudaFuncSetAttribute(fused_qkv_attn, cudaFuncAttributeMaxDynamicSharedMemorySize, FUSED_SMEM);

    ln_fused_kernel<<<MTOK / 32, 256>>>(x, ln_g, ln_b);
    wconv_kernel<<<(CCH * CCH + 6 * DD * DD + 255) / 256, 256>>>(
        conv_w, wqh, wkh, wvh, wqv, wkv, wvv);

    conv_gemm_mma<<<dim3(2, MTOK / 64), 256, GEMM_SMEM>>>(conv_b);

    fused_qkv_attn<<<dim3(NHEADS, BATCH * HWD, 2), 320, FUSED_SMEM>>>(
        out, bqh, bkh, bvh, bqv, bkv, bvv);
}